// round 1
// baseline (speedup 1.0000x reference)
#include <cuda_runtime.h>
#include <cuda_bf16.h>
#include <math.h>

// Problem dims
#define T_ 32
#define B_ 64
#define S_ 64
#define D_ 1024
#define D4_ 4096
#define TB_ 2048   // T*B

// ---------------- scratch (device globals; no cudaMalloc allowed) ----------------
__device__ float g_x0[TB_ * D_];    // embedded input        8 MB
__device__ float g_xg[TB_ * D4_];   // precomputed gates    32 MB (reused per layer)
__device__ float g_x1[TB_ * D_];    // layer0 outputs        8 MB
__device__ float g_x2[TB_ * D_];    // layer1 outputs        8 MB
__device__ float g_c [B_ * D_];     // cell state           256 KB
__device__ float g_q [TB_ * D_];    // attention query       8 MB
__device__ float g_cat[TB_ * 2 * D_]; // [weighted, x]      16 MB

// ---------------- embedding (padding_idx = 0) ----------------
__global__ void embed_kernel(const int* __restrict__ tok,
                             const float* __restrict__ emb,
                             float* __restrict__ x)
{
    int tb = blockIdx.x;          // 0..2047
    int t4 = threadIdx.x;         // 0..255 (float4 lanes, D/4 = 256)
    int tk = tok[tb];
    float4 v = make_float4(0.f, 0.f, 0.f, 0.f);
    if (tk != 0) v = ((const float4*)(emb + (size_t)tk * D_))[t4];
    ((float4*)(x + (size_t)tb * D_))[t4] = v;
}

// ---------------- SGEMM: C = A @ B^T (+epilogue) ----------------
// A: (M,K) row-major, B: (N,K) row-major, C: (M,N) row-major.
// All of M,N multiples of 128; K multiple of 16.
// EPI: 0 = none, 1 = +bias1[n]+bias2[n], 2 = tanh
template<int EPI>
__global__ __launch_bounds__(256)
void sgemm_nt(const float* __restrict__ A, const float* __restrict__ Bm,
              float* __restrict__ C, int M, int N, int K,
              const float* __restrict__ bias1, const float* __restrict__ bias2)
{
    __shared__ float As[16][128];
    __shared__ float Bs[16][128];

    const int tid = threadIdx.x;
    const int bm = blockIdx.y * 128;
    const int bn = blockIdx.x * 128;
    const int tx = tid & 15, ty = tid >> 4;

    float acc[8][8];
#pragma unroll
    for (int i = 0; i < 8; i++)
#pragma unroll
        for (int j = 0; j < 8; j++) acc[i][j] = 0.f;

    for (int k0 = 0; k0 < K; k0 += 16) {
        // load 128x16 tiles of A and B (transposed into smem)
#pragma unroll
        for (int i = 0; i < 2; i++) {
            int v = tid * 2 + i;        // 0..511 float4 id
            int row = v >> 2;
            int q = (v & 3) * 4;
            float4 a4 = *(const float4*)(A + (size_t)(bm + row) * K + k0 + q);
            As[q + 0][row] = a4.x; As[q + 1][row] = a4.y;
            As[q + 2][row] = a4.z; As[q + 3][row] = a4.w;
            float4 b4 = *(const float4*)(Bm + (size_t)(bn + row) * K + k0 + q);
            Bs[q + 0][row] = b4.x; Bs[q + 1][row] = b4.y;
            Bs[q + 2][row] = b4.z; Bs[q + 3][row] = b4.w;
        }
        __syncthreads();

#pragma unroll
        for (int kk = 0; kk < 16; kk++) {
            float a[8], b[8];
            *(float4*)(a)     = *(const float4*)&As[kk][ty * 8];
            *(float4*)(a + 4) = *(const float4*)&As[kk][ty * 8 + 4];
            *(float4*)(b)     = *(const float4*)&Bs[kk][tx * 8];
            *(float4*)(b + 4) = *(const float4*)&Bs[kk][tx * 8 + 4];
#pragma unroll
            for (int i = 0; i < 8; i++)
#pragma unroll
                for (int j = 0; j < 8; j++)
                    acc[i][j] = fmaf(a[i], b[j], acc[i][j]);
        }
        __syncthreads();
    }

#pragma unroll
    for (int i = 0; i < 8; i++) {
        int m = bm + ty * 8 + i;
        int n0 = bn + tx * 8;
        float v[8];
#pragma unroll
        for (int j = 0; j < 8; j++) {
            float x = acc[i][j];
            if (EPI == 1) x += bias1[n0 + j] + bias2[n0 + j];
            if (EPI == 2) x = tanhf(x);
            v[j] = x;
        }
        *(float4*)(C + (size_t)m * N + n0)     = *(float4*)(v);
        *(float4*)(C + (size_t)m * N + n0 + 4) = *(float4*)(v + 4);
    }
}

// ---------------- fused LSTM step ----------------
// gates = xg_t + hprev @ whh^T ; then pointwise. One block handles 8 d's for
// all 64 batches (32 whh rows: 4 gates x 8 d). grid = 128 blocks.
__global__ __launch_bounds__(256)
void lstm_step(const float* __restrict__ xg_t,   // (B, 4D)
               const float* __restrict__ hprev,  // (B, D)
               const float* __restrict__ whh,    // (4D, D)
               float* __restrict__ c,            // (B, D) in-place
               float* __restrict__ hout)         // (B, D)
{
    const int d0 = blockIdx.x * 8;
    __shared__ float hs[B_][128];     // 32 KB: K-chunk of h
    __shared__ float gsh[B_][32];     //  8 KB: staged gates

    const int tid = threadIdx.x;
    const int bpair = tid >> 3;       // 0..31
    const int rq = tid & 7;           // 0..7  -> rows rq*4 .. rq*4+3
    const int b0 = bpair * 2, b1 = b0 + 1;

    const float* wrow[4];
#pragma unroll
    for (int i = 0; i < 4; i++) {
        int rr = rq * 4 + i;
        int g = rr >> 3, dd = rr & 7;
        wrow[i] = whh + (size_t)(g * D_ + d0 + dd) * D_;
    }

    float acc0[4] = {0.f, 0.f, 0.f, 0.f};
    float acc1[4] = {0.f, 0.f, 0.f, 0.f};

    for (int k0 = 0; k0 < D_; k0 += 128) {
        __syncthreads();   // protect previous chunk's smem reads
        for (int v = tid; v < B_ * 32; v += 256) {  // float4 units
            int row = v >> 5, c4 = v & 31;
            ((float4*)hs[row])[c4] =
                ((const float4*)(hprev + (size_t)row * D_ + k0))[c4];
        }
        __syncthreads();

#pragma unroll 8
        for (int kk = 0; kk < 32; kk++) {   // float4 steps over the chunk
            float4 ha = ((const float4*)hs[b0])[kk];
            float4 hb = ((const float4*)hs[b1])[kk];
#pragma unroll
            for (int i = 0; i < 4; i++) {
                float4 w = __ldg((const float4*)(wrow[i] + k0) + kk);
                acc0[i] = fmaf(ha.x, w.x, acc0[i]);
                acc0[i] = fmaf(ha.y, w.y, acc0[i]);
                acc0[i] = fmaf(ha.z, w.z, acc0[i]);
                acc0[i] = fmaf(ha.w, w.w, acc0[i]);
                acc1[i] = fmaf(hb.x, w.x, acc1[i]);
                acc1[i] = fmaf(hb.y, w.y, acc1[i]);
                acc1[i] = fmaf(hb.z, w.z, acc1[i]);
                acc1[i] = fmaf(hb.w, w.w, acc1[i]);
            }
        }
    }

    // add precomputed input gates, stage into smem
#pragma unroll
    for (int i = 0; i < 4; i++) {
        int rr = rq * 4 + i;
        int g = rr >> 3, dd = rr & 7;
        int col = g * D_ + d0 + dd;
        gsh[b0][rr] = acc0[i] + xg_t[(size_t)b0 * D4_ + col];
        gsh[b1][rr] = acc1[i] + xg_t[(size_t)b1 * D4_ + col];
    }
    __syncthreads();

    // pointwise: 64 b x 8 dd = 512 outputs
    for (int o = tid; o < 512; o += 256) {
        int b = o >> 3, dd = o & 7;
        float ig = gsh[b][0 * 8 + dd];
        float fg = gsh[b][1 * 8 + dd];
        float gg = gsh[b][2 * 8 + dd];
        float og = gsh[b][3 * 8 + dd];
        size_t idx = (size_t)b * D_ + d0 + dd;
        float ci = c[idx];
        float i_ = 1.f / (1.f + __expf(-ig));
        float f_ = 1.f / (1.f + __expf(-fg));
        float o_ = 1.f / (1.f + __expf(-og));
        float cn = f_ * ci + i_ * tanhf(gg);
        float hn = o_ * tanhf(cn);
        c[idx] = cn;
        hout[idx] = hn;
    }
}

// ---------------- attention: scores + softmax + weighted + cat ----------------
// one block per (t,b); 256 threads
__global__ __launch_bounds__(256)
void attn_kernel(const float* __restrict__ q,      // (T*B, D)
                 const float* __restrict__ ctx,    // (S, B, D)
                 const float* __restrict__ x,      // (T*B, D)
                 float* __restrict__ cat,          // (T*B, 2D)
                 float* __restrict__ attn_out)     // (B, S), written at t=T-1
{
    const int b = blockIdx.x;
    const int t = blockIdx.y;
    const int tb = t * B_ + b;
    __shared__ float qs[D_];
    __shared__ float sc[S_];

    const int tid = threadIdx.x;
    const int warp = tid >> 5, lane = tid & 31;

    ((float4*)qs)[tid] = ((const float4*)(q + (size_t)tb * D_))[tid];
    __syncthreads();

    // scores: warp w handles s = w*8 .. w*8+7
#pragma unroll
    for (int si = 0; si < 8; si++) {
        int s = warp * 8 + si;
        const float4* crow = (const float4*)(ctx + (size_t)(s * B_ + b) * D_);
        float sum = 0.f;
#pragma unroll
        for (int i = 0; i < 8; i++) {
            float4 cv = crow[lane + 32 * i];
            float4 qv = ((const float4*)qs)[lane + 32 * i];
            sum = fmaf(cv.x, qv.x, sum);
            sum = fmaf(cv.y, qv.y, sum);
            sum = fmaf(cv.z, qv.z, sum);
            sum = fmaf(cv.w, qv.w, sum);
        }
#pragma unroll
        for (int off = 16; off; off >>= 1)
            sum += __shfl_down_sync(0xffffffffu, sum, off);
        if (lane == 0) sc[s] = sum;
    }
    __syncthreads();

    // softmax over 64 values (warp 0)
    if (warp == 0) {
        float v0 = sc[lane], v1 = sc[lane + 32];
        float m = fmaxf(v0, v1);
#pragma unroll
        for (int off = 16; off; off >>= 1)
            m = fmaxf(m, __shfl_xor_sync(0xffffffffu, m, off));
        float e0 = __expf(v0 - m), e1 = __expf(v1 - m);
        float ssum = e0 + e1;
#pragma unroll
        for (int off = 16; off; off >>= 1)
            ssum += __shfl_xor_sync(0xffffffffu, ssum, off);
        float inv = 1.f / ssum;
        sc[lane] = e0 * inv;
        sc[lane + 32] = e1 * inv;
    }
    __syncthreads();

    // weighted sum + write cat = [weighted, x]
    float4 accv = make_float4(0.f, 0.f, 0.f, 0.f);
    for (int s = 0; s < S_; s++) {
        float a = sc[s];
        float4 cv = ((const float4*)(ctx + (size_t)(s * B_ + b) * D_))[tid];
        accv.x = fmaf(a, cv.x, accv.x);
        accv.y = fmaf(a, cv.y, accv.y);
        accv.z = fmaf(a, cv.z, accv.z);
        accv.w = fmaf(a, cv.w, accv.w);
    }
    ((float4*)(cat + (size_t)tb * 2 * D_))[tid] = accv;
    ((float4*)(cat + (size_t)tb * 2 * D_ + D_))[tid] =
        ((const float4*)(x + (size_t)tb * D_))[tid];

    if (t == T_ - 1 && tid < S_) attn_out[b * S_ + tid] = sc[tid];
}

// ---------------- launch ----------------
extern "C" void kernel_launch(void* const* d_in, const int* in_sizes, int n_in,
                              void* d_out, int out_size)
{
    (void)in_sizes; (void)n_in; (void)out_size;

    const int*   input = (const int*)  d_in[0];
    const float* h0    = (const float*)d_in[1];   // (L,B,D)
    const float* c0    = (const float*)d_in[2];   // (L,B,D)
    const float* ctx   = (const float*)d_in[3];   // (S,B,D)
    // d_in[4] init_output: unused by reference
    const float* emb   = (const float*)d_in[5];   // (V,D)
    const float* wih0  = (const float*)d_in[6];
    const float* whh0  = (const float*)d_in[7];
    const float* bih0  = (const float*)d_in[8];
    const float* bhh0  = (const float*)d_in[9];
    const float* wih1  = (const float*)d_in[10];
    const float* whh1  = (const float*)d_in[11];
    const float* bih1  = (const float*)d_in[12];
    const float* bhh1  = (const float*)d_in[13];
    const float* w_in  = (const float*)d_in[14];  // (D,D)
    const float* w_out = (const float*)d_in[15];  // (D,2D)

    float* out      = (float*)d_out;                       // (T,B,D)
    float* out_hn   = out + (size_t)TB_ * D_;              // (L,B,D)
    float* out_cn   = out_hn + (size_t)2 * B_ * D_;        // (L,B,D)
    float* out_attn = out_cn + (size_t)2 * B_ * D_;        // (B,S)

    float *x0, *xg, *x1, *x2, *c, *q, *cat;
    cudaGetSymbolAddress((void**)&x0,  g_x0);
    cudaGetSymbolAddress((void**)&xg,  g_xg);
    cudaGetSymbolAddress((void**)&x1,  g_x1);
    cudaGetSymbolAddress((void**)&x2,  g_x2);
    cudaGetSymbolAddress((void**)&c,   g_c);
    cudaGetSymbolAddress((void**)&q,   g_q);
    cudaGetSymbolAddress((void**)&cat, g_cat);

    const size_t BD = (size_t)B_ * D_;

    // 1) embedding
    embed_kernel<<<TB_, 256>>>(input, emb, x0);

    // 2) layer 0: input gates GEMM, then 32 recurrent steps
    sgemm_nt<1><<<dim3(D4_ / 128, TB_ / 128), 256>>>(
        x0, wih0, xg, TB_, D4_, D_, bih0, bhh0);
    cudaMemcpyAsync(c, c0, BD * sizeof(float), cudaMemcpyDeviceToDevice, 0);
    for (int t = 0; t < T_; t++) {
        const float* hprev = (t == 0) ? h0 : (x1 + (size_t)(t - 1) * BD);
        lstm_step<<<128, 256>>>(xg + (size_t)t * B_ * D4_, hprev, whh0,
                                c, x1 + (size_t)t * BD);
    }
    cudaMemcpyAsync(out_hn, x1 + (size_t)(T_ - 1) * BD, BD * sizeof(float),
                    cudaMemcpyDeviceToDevice, 0);
    cudaMemcpyAsync(out_cn, c, BD * sizeof(float), cudaMemcpyDeviceToDevice, 0);

    // 3) layer 1
    sgemm_nt<1><<<dim3(D4_ / 128, TB_ / 128), 256>>>(
        x1, wih1, xg, TB_, D4_, D_, bih1, bhh1);
    cudaMemcpyAsync(c, c0 + BD, BD * sizeof(float), cudaMemcpyDeviceToDevice, 0);
    for (int t = 0; t < T_; t++) {
        const float* hprev = (t == 0) ? (h0 + BD) : (x2 + (size_t)(t - 1) * BD);
        lstm_step<<<128, 256>>>(xg + (size_t)t * B_ * D4_, hprev, whh1,
                                c, x2 + (size_t)t * BD);
    }
    cudaMemcpyAsync(out_hn + BD, x2 + (size_t)(T_ - 1) * BD, BD * sizeof(float),
                    cudaMemcpyDeviceToDevice, 0);
    cudaMemcpyAsync(out_cn + BD, c, BD * sizeof(float), cudaMemcpyDeviceToDevice, 0);

    // 4) attention: q = x @ w_in^T ; scores/softmax/weighted ; cat
    sgemm_nt<0><<<dim3(D_ / 128, TB_ / 128), 256>>>(
        x2, w_in, q, TB_, D_, D_, nullptr, nullptr);
    attn_kernel<<<dim3(B_, T_), 256>>>(q, ctx, x2, cat, out_attn);

    // 5) out = tanh(cat @ w_out^T)
    sgemm_nt<2><<<dim3(D_ / 128, TB_ / 128), 256>>>(
        cat, w_out, out, TB_, D_, 2 * D_, nullptr, nullptr);
}

// round 2
// speedup vs baseline: 2.9139x; 2.9139x over previous
#include <cuda_runtime.h>
#include <cuda_bf16.h>
#include <math.h>

// Problem dims
#define T_ 32
#define B_ 64
#define S_ 64
#define D_ 1024
#define D4_ 4096
#define TB_ 2048   // T*B

// ---------------- scratch (device globals; no cudaMalloc allowed) ----------------
__device__ float g_x0[TB_ * D_];    // embedded input        8 MB
__device__ float g_xg[TB_ * D4_];   // precomputed gates    32 MB (reused per layer)
__device__ float g_x1[TB_ * D_];    // layer0 outputs        8 MB
__device__ float g_x2[TB_ * D_];    // layer1 outputs        8 MB
__device__ float g_c [B_ * D_];     // cell state           256 KB
__device__ float g_q [TB_ * D_];    // attention query       8 MB
__device__ float g_cat[TB_ * 2 * D_]; // [weighted, x]      16 MB

// ---------------- f32x2 helpers (Blackwell packed fp32) ----------------
__device__ __forceinline__ void fma2(unsigned long long& d,
                                     unsigned long long a,
                                     unsigned long long b)
{
    asm("fma.rn.f32x2 %0, %1, %2, %0;" : "+l"(d) : "l"(a), "l"(b));
}
__device__ __forceinline__ unsigned long long dup2(float a)
{
    unsigned long long r;
    asm("mov.b64 %0, {%1, %1};" : "=l"(r) : "r"(__float_as_uint(a)));
    return r;
}
__device__ __forceinline__ float pairsum(unsigned long long v)
{
    unsigned int lo, hi;
    asm("mov.b64 {%0, %1}, %2;" : "=r"(lo), "=r"(hi) : "l"(v));
    return __uint_as_float(lo) + __uint_as_float(hi);
}
__device__ __forceinline__ void unpack2(unsigned long long v, float& a, float& b)
{
    unsigned int lo, hi;
    asm("mov.b64 {%0, %1}, %2;" : "=r"(lo), "=r"(hi) : "l"(v));
    a = __uint_as_float(lo);
    b = __uint_as_float(hi);
}

// ---------------- embedding (padding_idx = 0) ----------------
__global__ void embed_kernel(const int* __restrict__ tok,
                             const float* __restrict__ emb,
                             float* __restrict__ x)
{
    int tb = blockIdx.x;          // 0..2047
    int t4 = threadIdx.x;         // 0..255 (float4 lanes, D/4 = 256)
    int tk = tok[tb];
    float4 v = make_float4(0.f, 0.f, 0.f, 0.f);
    if (tk != 0) v = ((const float4*)(emb + (size_t)tk * D_))[t4];
    ((float4*)(x + (size_t)tb * D_))[t4] = v;
}

// ---------------- SGEMM: C = A @ B^T (+epilogue), f32x2 inner ----------------
// A: (M,K) row-major, B: (N,K) row-major, C: (M,N) row-major.
// M,N multiples of 128; K multiple of 16.
// EPI: 0 = none, 1 = +bias1[n]+bias2[n], 2 = tanh
template<int EPI>
__global__ __launch_bounds__(256)
void sgemm_nt(const float* __restrict__ A, const float* __restrict__ Bm,
              float* __restrict__ C, int M, int N, int K,
              const float* __restrict__ bias1, const float* __restrict__ bias2)
{
    __shared__ float As[16][128];
    __shared__ float Bs[16][128];

    const int tid = threadIdx.x;
    const int bm = blockIdx.y * 128;
    const int bn = blockIdx.x * 128;
    const int tx = tid & 15, ty = tid >> 4;

    unsigned long long acc[8][4];   // [m][n-pair]: each holds (n2p, n2p+1)
#pragma unroll
    for (int i = 0; i < 8; i++)
#pragma unroll
        for (int j = 0; j < 4; j++) acc[i][j] = 0ULL;

    for (int k0 = 0; k0 < K; k0 += 16) {
        // load 128x16 tiles of A and B (transposed into smem)
#pragma unroll
        for (int i = 0; i < 2; i++) {
            int v = tid * 2 + i;        // 0..511 float4 id
            int row = v >> 2;
            int q = (v & 3) * 4;
            float4 a4 = *(const float4*)(A + (size_t)(bm + row) * K + k0 + q);
            As[q + 0][row] = a4.x; As[q + 1][row] = a4.y;
            As[q + 2][row] = a4.z; As[q + 3][row] = a4.w;
            float4 b4 = *(const float4*)(Bm + (size_t)(bn + row) * K + k0 + q);
            Bs[q + 0][row] = b4.x; Bs[q + 1][row] = b4.y;
            Bs[q + 2][row] = b4.z; Bs[q + 3][row] = b4.w;
        }
        __syncthreads();

#pragma unroll
        for (int kk = 0; kk < 16; kk++) {
            float a[8];
            *(float4*)(a)     = *(const float4*)&As[kk][ty * 8];
            *(float4*)(a + 4) = *(const float4*)&As[kk][ty * 8 + 4];
            ulonglong2 bq0 = *(const ulonglong2*)&Bs[kk][tx * 8];
            ulonglong2 bq1 = *(const ulonglong2*)&Bs[kk][tx * 8 + 4];
#pragma unroll
            for (int i = 0; i < 8; i++) {
                unsigned long long ad = dup2(a[i]);
                fma2(acc[i][0], ad, bq0.x);
                fma2(acc[i][1], ad, bq0.y);
                fma2(acc[i][2], ad, bq1.x);
                fma2(acc[i][3], ad, bq1.y);
            }
        }
        __syncthreads();
    }

#pragma unroll
    for (int i = 0; i < 8; i++) {
        int m = bm + ty * 8 + i;
        int n0 = bn + tx * 8;
        float v[8];
#pragma unroll
        for (int p = 0; p < 4; p++) unpack2(acc[i][p], v[2 * p], v[2 * p + 1]);
#pragma unroll
        for (int j = 0; j < 8; j++) {
            float x = v[j];
            if (EPI == 1) x += bias1[n0 + j] + bias2[n0 + j];
            if (EPI == 2) x = tanhf(x);
            v[j] = x;
        }
        *(float4*)(C + (size_t)m * N + n0)     = *(float4*)(v);
        *(float4*)(C + (size_t)m * N + n0 + 4) = *(float4*)(v + 4);
    }
}

// ---------------- fused LSTM step (smem-staged, f32x2) ----------------
// Block handles 8 output dims (d0..d0+7), all 4 gates, all 64 batches.
// Thread (ni = tid&7 -> dim, bi = tid>>3 -> 2 batches). grid=128, 256 threads.
// gates = xg_t + hprev @ whh^T; pointwise fully thread-local.
#define LCH 128          // k-chunk staged in smem
#define LPAD 132         // padded row stride (floats); 132*4 B is 16B-aligned

__global__ __launch_bounds__(256, 1)
void lstm_step(const float* __restrict__ xg_t,   // (B, 4D)
               const float* __restrict__ hprev,  // (B, D)
               const float* __restrict__ whh,    // (4D, D)
               float* __restrict__ c,            // (B, D) in-place
               float* __restrict__ hout)         // (B, D)
{
    __shared__ float hs[B_][LPAD];   // 64 x 132 floats  (33.8 KB)
    __shared__ float ws[32][LPAD];   // 32 x 132 floats  (16.9 KB)

    const int tid = threadIdx.x;
    const int ni = tid & 7;          // dim within block
    const int bi = tid >> 3;         // 0..31
    const int d0 = blockIdx.x << 3;
    const int d  = d0 + ni;
    const int b0 = bi << 1;          // 2 batches per thread

    unsigned long long acc[4][2];    // [gate][batch], k-paired partial sums
#pragma unroll
    for (int g = 0; g < 4; g++) { acc[g][0] = 0ULL; acc[g][1] = 0ULL; }

    for (int base = 0; base < D_; base += LCH) {
        __syncthreads();
        // stage h chunk: 64 rows x 32 float4
        for (int v = tid; v < B_ * (LCH / 4); v += 256) {
            int r = v >> 5, q = v & 31;
            *(float4*)&hs[r][q * 4] =
                *(const float4*)(hprev + (size_t)r * D_ + base + q * 4);
        }
        // stage w slice: rows r = g*8 + nn  -> whh row (g*1024 + d0 + nn)
        for (int v = tid; v < 32 * (LCH / 4); v += 256) {
            int r = v >> 5, q = v & 31;
            int g = r >> 3, nn = r & 7;
            *(float4*)&ws[r][q * 4] =
                *(const float4*)(whh + ((size_t)(g << 10) + d0 + nn) * D_ + base + q * 4);
        }
        __syncthreads();

#pragma unroll 2
        for (int kk = 0; kk < LCH; kk += 8) {
            ulonglong2 hv[2][2];
#pragma unroll
            for (int j = 0; j < 2; j++) {
                hv[j][0] = *(const ulonglong2*)&hs[b0 + j][kk];
                hv[j][1] = *(const ulonglong2*)&hs[b0 + j][kk + 4];
            }
            ulonglong2 wv[4][2];
#pragma unroll
            for (int g = 0; g < 4; g++) {
                wv[g][0] = *(const ulonglong2*)&ws[(g << 3) + ni][kk];
                wv[g][1] = *(const ulonglong2*)&ws[(g << 3) + ni][kk + 4];
            }
#pragma unroll
            for (int g = 0; g < 4; g++)
#pragma unroll
                for (int j = 0; j < 2; j++) {
                    fma2(acc[g][j], hv[j][0].x, wv[g][0].x);
                    fma2(acc[g][j], hv[j][0].y, wv[g][0].y);
                    fma2(acc[g][j], hv[j][1].x, wv[g][1].x);
                    fma2(acc[g][j], hv[j][1].y, wv[g][1].y);
                }
        }
    }

    // pointwise, fully thread-local
#pragma unroll
    for (int j = 0; j < 2; j++) {
        int b = b0 + j;
        float ig = pairsum(acc[0][j]) + xg_t[(size_t)b * D4_ + 0 * D_ + d];
        float fg = pairsum(acc[1][j]) + xg_t[(size_t)b * D4_ + 1 * D_ + d];
        float gg = pairsum(acc[2][j]) + xg_t[(size_t)b * D4_ + 2 * D_ + d];
        float og = pairsum(acc[3][j]) + xg_t[(size_t)b * D4_ + 3 * D_ + d];
        size_t idx = (size_t)b * D_ + d;
        float ci = c[idx];
        float i_ = 1.f / (1.f + __expf(-ig));
        float f_ = 1.f / (1.f + __expf(-fg));
        float o_ = 1.f / (1.f + __expf(-og));
        float cn = f_ * ci + i_ * tanhf(gg);
        float hn = o_ * tanhf(cn);
        c[idx] = cn;
        hout[idx] = hn;
    }
}

// ---------------- attention: scores + softmax + weighted + cat ----------------
// one block per (t,b); 256 threads
__global__ __launch_bounds__(256)
void attn_kernel(const float* __restrict__ q,      // (T*B, D)
                 const float* __restrict__ ctx,    // (S, B, D)
                 const float* __restrict__ x,      // (T*B, D)
                 float* __restrict__ cat,          // (T*B, 2D)
                 float* __restrict__ attn_out)     // (B, S), written at t=T-1
{
    const int b = blockIdx.x;
    const int t = blockIdx.y;
    const int tb = t * B_ + b;
    __shared__ float qs[D_];
    __shared__ float sc[S_];

    const int tid = threadIdx.x;
    const int warp = tid >> 5, lane = tid & 31;

    ((float4*)qs)[tid] = ((const float4*)(q + (size_t)tb * D_))[tid];
    __syncthreads();

#pragma unroll
    for (int si = 0; si < 8; si++) {
        int s = warp * 8 + si;
        const float4* crow = (const float4*)(ctx + (size_t)(s * B_ + b) * D_);
        float sum = 0.f;
#pragma unroll
        for (int i = 0; i < 8; i++) {
            float4 cv = crow[lane + 32 * i];
            float4 qv = ((const float4*)qs)[lane + 32 * i];
            sum = fmaf(cv.x, qv.x, sum);
            sum = fmaf(cv.y, qv.y, sum);
            sum = fmaf(cv.z, qv.z, sum);
            sum = fmaf(cv.w, qv.w, sum);
        }
#pragma unroll
        for (int off = 16; off; off >>= 1)
            sum += __shfl_down_sync(0xffffffffu, sum, off);
        if (lane == 0) sc[s] = sum;
    }
    __syncthreads();

    if (warp == 0) {
        float v0 = sc[lane], v1 = sc[lane + 32];
        float m = fmaxf(v0, v1);
#pragma unroll
        for (int off = 16; off; off >>= 1)
            m = fmaxf(m, __shfl_xor_sync(0xffffffffu, m, off));
        float e0 = __expf(v0 - m), e1 = __expf(v1 - m);
        float ssum = e0 + e1;
#pragma unroll
        for (int off = 16; off; off >>= 1)
            ssum += __shfl_xor_sync(0xffffffffu, ssum, off);
        float inv = 1.f / ssum;
        sc[lane] = e0 * inv;
        sc[lane + 32] = e1 * inv;
    }
    __syncthreads();

    float4 accv = make_float4(0.f, 0.f, 0.f, 0.f);
    for (int s = 0; s < S_; s++) {
        float a = sc[s];
        float4 cv = ((const float4*)(ctx + (size_t)(s * B_ + b) * D_))[tid];
        accv.x = fmaf(a, cv.x, accv.x);
        accv.y = fmaf(a, cv.y, accv.y);
        accv.z = fmaf(a, cv.z, accv.z);
        accv.w = fmaf(a, cv.w, accv.w);
    }
    ((float4*)(cat + (size_t)tb * 2 * D_))[tid] = accv;
    ((float4*)(cat + (size_t)tb * 2 * D_ + D_))[tid] =
        ((const float4*)(x + (size_t)tb * D_))[tid];

    if (t == T_ - 1 && tid < S_) attn_out[b * S_ + tid] = sc[tid];
}

// ---------------- launch ----------------
extern "C" void kernel_launch(void* const* d_in, const int* in_sizes, int n_in,
                              void* d_out, int out_size)
{
    (void)in_sizes; (void)n_in; (void)out_size;

    const int*   input = (const int*)  d_in[0];
    const float* h0    = (const float*)d_in[1];   // (L,B,D)
    const float* c0    = (const float*)d_in[2];   // (L,B,D)
    const float* ctx   = (const float*)d_in[3];   // (S,B,D)
    const float* emb   = (const float*)d_in[5];   // (V,D)
    const float* wih0  = (const float*)d_in[6];
    const float* whh0  = (const float*)d_in[7];
    const float* bih0  = (const float*)d_in[8];
    const float* bhh0  = (const float*)d_in[9];
    const float* wih1  = (const float*)d_in[10];
    const float* whh1  = (const float*)d_in[11];
    const float* bih1  = (const float*)d_in[12];
    const float* bhh1  = (const float*)d_in[13];
    const float* w_in  = (const float*)d_in[14];  // (D,D)
    const float* w_out = (const float*)d_in[15];  // (D,2D)

    float* out      = (float*)d_out;                       // (T,B,D)
    float* out_hn   = out + (size_t)TB_ * D_;              // (L,B,D)
    float* out_cn   = out_hn + (size_t)2 * B_ * D_;        // (L,B,D)
    float* out_attn = out_cn + (size_t)2 * B_ * D_;        // (B,S)

    float *x0, *xg, *x1, *x2, *c, *q, *cat;
    cudaGetSymbolAddress((void**)&x0,  g_x0);
    cudaGetSymbolAddress((void**)&xg,  g_xg);
    cudaGetSymbolAddress((void**)&x1,  g_x1);
    cudaGetSymbolAddress((void**)&x2,  g_x2);
    cudaGetSymbolAddress((void**)&c,   g_c);
    cudaGetSymbolAddress((void**)&q,   g_q);
    cudaGetSymbolAddress((void**)&cat, g_cat);

    const size_t BD = (size_t)B_ * D_;

    // 1) embedding
    embed_kernel<<<TB_, 256>>>(input, emb, x0);

    // 2) layer 0: input gates GEMM, then 32 recurrent steps
    sgemm_nt<1><<<dim3(D4_ / 128, TB_ / 128), 256>>>(
        x0, wih0, xg, TB_, D4_, D_, bih0, bhh0);
    cudaMemcpyAsync(c, c0, BD * sizeof(float), cudaMemcpyDeviceToDevice, 0);
    for (int t = 0; t < T_; t++) {
        const float* hprev = (t == 0) ? h0 : (x1 + (size_t)(t - 1) * BD);
        lstm_step<<<128, 256>>>(xg + (size_t)t * B_ * D4_, hprev, whh0,
                                c, x1 + (size_t)t * BD);
    }
    cudaMemcpyAsync(out_hn, x1 + (size_t)(T_ - 1) * BD, BD * sizeof(float),
                    cudaMemcpyDeviceToDevice, 0);
    cudaMemcpyAsync(out_cn, c, BD * sizeof(float), cudaMemcpyDeviceToDevice, 0);

    // 3) layer 1
    sgemm_nt<1><<<dim3(D4_ / 128, TB_ / 128), 256>>>(
        x1, wih1, xg, TB_, D4_, D_, bih1, bhh1);
    cudaMemcpyAsync(c, c0 + BD, BD * sizeof(float), cudaMemcpyDeviceToDevice, 0);
    for (int t = 0; t < T_; t++) {
        const float* hprev = (t == 0) ? (h0 + BD) : (x2 + (size_t)(t - 1) * BD);
        lstm_step<<<128, 256>>>(xg + (size_t)t * B_ * D4_, hprev, whh1,
                                c, x2 + (size_t)t * BD);
    }
    cudaMemcpyAsync(out_hn + BD, x2 + (size_t)(T_ - 1) * BD, BD * sizeof(float),
                    cudaMemcpyDeviceToDevice, 0);
    cudaMemcpyAsync(out_cn + BD, c, BD * sizeof(float), cudaMemcpyDeviceToDevice, 0);

    // 4) attention
    sgemm_nt<0><<<dim3(D_ / 128, TB_ / 128), 256>>>(
        x2, w_in, q, TB_, D_, D_, nullptr, nullptr);
    attn_kernel<<<dim3(B_, T_), 256>>>(q, ctx, x2, cat, out_attn);

    // 5) out = tanh(cat @ w_out^T)
    sgemm_nt<2><<<dim3(D_ / 128, TB_ / 128), 256>>>(
        cat, w_out, out, TB_, D_, 2 * D_, nullptr, nullptr);
}